// round 1
// baseline (speedup 1.0000x reference)
#include <cuda_runtime.h>

#define B_ 4
#define T_ 4096
#define C_ 512
#define H_ 64

// Scratch for projected k,q,v: [B,T,H] each (12.6 MB total) — __device__ globals per rules.
__device__ float g_k[B_ * T_ * H_];
__device__ float g_q[B_ * T_ * H_];
__device__ float g_v[B_ * T_ * H_];

// ---------------------------------------------------------------------------
// Kernel 1: QKV projection. out[m][n] = sum_k x[m][k] * W[k][n] + b[n]
// M = B*T = 16384, N = 64 per matrix, K = 512. blockIdx.y selects k/q/v.
// BM=64, BN=64, BK=32; 256 threads as 16x16, 4x4 register tile.
// ---------------------------------------------------------------------------
__global__ __launch_bounds__(256) void qkv_kernel(
    const float* __restrict__ x,
    const float* __restrict__ Wk, const float* __restrict__ bk,
    const float* __restrict__ Wq, const float* __restrict__ bq,
    const float* __restrict__ Wv, const float* __restrict__ bv) {
  __shared__ float As[64][33];   // x chunk [row][kk], pad 33 (scalar reads)
  __shared__ float Bs[32][68];   // W chunk [kk][col], pad 68 (float4 reads, 16B-aligned rows)

  const float* W;
  const float* bias;
  float* out;
  if (blockIdx.y == 0)      { W = Wk; bias = bk; out = g_k; }
  else if (blockIdx.y == 1) { W = Wq; bias = bq; out = g_q; }
  else                      { W = Wv; bias = bv; out = g_v; }

  const int row0 = blockIdx.x * 64;
  const int tid = threadIdx.x;
  const int ty = tid >> 4;
  const int tx = tid & 15;

  float acc[4][4] = {};

  for (int kc = 0; kc < C_; kc += 32) {
    // Load x chunk [64][32] — warp-coalesced (lane covers one 32-wide row chunk)
    #pragma unroll
    for (int i = tid; i < 64 * 32; i += 256) {
      int r = i >> 5, kk = i & 31;
      As[r][kk] = x[(size_t)(row0 + r) * C_ + kc + kk];
    }
    // Load W chunk [32][64] — coalesced over col
    #pragma unroll
    for (int i = tid; i < 32 * 64; i += 256) {
      int kk = i >> 6, col = i & 63;
      Bs[kk][col] = W[(kc + kk) * H_ + col];
    }
    __syncthreads();

    #pragma unroll
    for (int kk = 0; kk < 32; kk++) {
      float4 w4 = *reinterpret_cast<const float4*>(&Bs[kk][tx * 4]);
      #pragma unroll
      for (int r = 0; r < 4; r++) {
        float a = As[4 * ty + r][kk];
        acc[r][0] += a * w4.x;
        acc[r][1] += a * w4.y;
        acc[r][2] += a * w4.z;
        acc[r][3] += a * w4.w;
      }
    }
    __syncthreads();
  }

  float4 b4 = *reinterpret_cast<const float4*>(&bias[tx * 4]);
  #pragma unroll
  for (int r = 0; r < 4; r++) {
    float4 res = make_float4(acc[r][0] + b4.x, acc[r][1] + b4.y,
                             acc[r][2] + b4.z, acc[r][3] + b4.w);
    *reinterpret_cast<float4*>(&out[(size_t)(row0 + 4 * ty + r) * H_ + tx * 4]) = res;
  }
}

// ---------------------------------------------------------------------------
// Kernel 2: flash attention. Roles per the reference: rows = k (output rows),
// softmax over q axis, values = v.
// Per block: 64 k-rows; loop over q in tiles of 32. 256 threads (16x16).
// S register tile 4x2 (rows 4ty+r, cols 2tx+c), O tile 4x4 (h = 4tx+c).
// ---------------------------------------------------------------------------
__global__ __launch_bounds__(256) void attn_kernel(float* __restrict__ out) {
  __shared__ float ks[64][68];  // k tile (pre-scaled), pad 68 -> float4 row reads
  __shared__ float qs[32][65];  // q tile, pad 65 -> conflict-light scalar reads
  __shared__ float vs[32][68];  // v tile, pad 68 -> float4 reads vs[j][4tx..]
  __shared__ float Ps[64][33];  // probabilities staging

  const int b = blockIdx.y;
  const int row0 = blockIdx.x * 64;
  const int tid = threadIdx.x;
  const int ty = tid >> 4;
  const int tx = tid & 15;
  const float scale = 0.04419417382415922f;  // 512^-0.5

  const float* kg = g_k + (size_t)b * T_ * H_;
  const float* qg = g_q + (size_t)b * T_ * H_;
  const float* vg = g_v + (size_t)b * T_ * H_;

  // Load K tile once, fold in scale
  for (int i = tid; i < 64 * 64; i += 256) {
    int r = i >> 6, h = i & 63;
    ks[r][h] = kg[(size_t)(row0 + r) * H_ + h] * scale;
  }

  float m[4], l[4], o[4][4];
  #pragma unroll
  for (int r = 0; r < 4; r++) {
    m[r] = -1e30f;
    l[r] = 0.0f;
    #pragma unroll
    for (int c = 0; c < 4; c++) o[r][c] = 0.0f;
  }
  __syncthreads();

  for (int jt = 0; jt < T_; jt += 32) {
    // Load q/v tiles [32][64], coalesced
    #pragma unroll
    for (int i = tid; i < 32 * 64; i += 256) {
      int j = i >> 6, h = i & 63;
      qs[j][h] = qg[(size_t)(jt + j) * H_ + h];
      vs[j][h] = vg[(size_t)(jt + j) * H_ + h];
    }
    __syncthreads();

    // S[r][c] = sum_h ks[4ty+r][h] * qs[2tx+c][h]
    float s[4][2] = {};
    #pragma unroll
    for (int h4 = 0; h4 < 16; h4++) {
      float4 a[4];
      #pragma unroll
      for (int r = 0; r < 4; r++)
        a[r] = *reinterpret_cast<const float4*>(&ks[4 * ty + r][4 * h4]);
      #pragma unroll
      for (int c = 0; c < 2; c++) {
        const float* qrow = &qs[2 * tx + c][4 * h4];
        float b0 = qrow[0], b1 = qrow[1], b2 = qrow[2], b3 = qrow[3];
        #pragma unroll
        for (int r = 0; r < 4; r++)
          s[r][c] += a[r].x * b0 + a[r].y * b1 + a[r].z * b2 + a[r].w * b3;
      }
    }

    // Online softmax per row (reduce across 16 tx lanes via shfl.bfly)
    #pragma unroll
    for (int r = 0; r < 4; r++) {
      float mr = fmaxf(s[r][0], s[r][1]);
      #pragma unroll
      for (int d = 8; d >= 1; d >>= 1)
        mr = fmaxf(mr, __shfl_xor_sync(0xffffffffu, mr, d));
      float mnew = fmaxf(m[r], mr);
      float p0 = __expf(s[r][0] - mnew);
      float p1 = __expf(s[r][1] - mnew);
      float alpha = __expf(m[r] - mnew);
      float ls = p0 + p1;
      #pragma unroll
      for (int d = 8; d >= 1; d >>= 1)
        ls += __shfl_xor_sync(0xffffffffu, ls, d);
      l[r] = l[r] * alpha + ls;
      m[r] = mnew;
      #pragma unroll
      for (int c = 0; c < 4; c++) o[r][c] *= alpha;
      Ps[4 * ty + r][2 * tx]     = p0;
      Ps[4 * ty + r][2 * tx + 1] = p1;
    }
    __syncthreads();

    // O += P @ V  (reduce over j; h cols = 4tx..4tx+3 via float4)
    #pragma unroll
    for (int j = 0; j < 32; j++) {
      float4 v4 = *reinterpret_cast<const float4*>(&vs[j][4 * tx]);
      #pragma unroll
      for (int r = 0; r < 4; r++) {
        float p = Ps[4 * ty + r][j];
        o[r][0] += p * v4.x;
        o[r][1] += p * v4.y;
        o[r][2] += p * v4.z;
        o[r][3] += p * v4.w;
      }
    }
    __syncthreads();
  }

  #pragma unroll
  for (int r = 0; r < 4; r++) {
    float inv = 1.0f / l[r];
    float4 res = make_float4(o[r][0] * inv, o[r][1] * inv,
                             o[r][2] * inv, o[r][3] * inv);
    *reinterpret_cast<float4*>(
        &out[((size_t)b * T_ + row0 + 4 * ty + r) * H_ + 4 * tx]) = res;
  }
}

extern "C" void kernel_launch(void* const* d_in, const int* in_sizes, int n_in,
                              void* d_out, int out_size) {
  const float* x  = (const float*)d_in[0];
  const float* Wk = (const float*)d_in[1];
  const float* bk = (const float*)d_in[2];
  const float* Wq = (const float*)d_in[3];
  const float* bq = (const float*)d_in[4];
  const float* Wv = (const float*)d_in[5];
  const float* bv = (const float*)d_in[6];
  float* out = (float*)d_out;

  dim3 qkv_grid((B_ * T_) / 64, 3);
  qkv_kernel<<<qkv_grid, 256>>>(x, Wk, bk, Wq, bq, Wv, bv);

  dim3 attn_grid(T_ / 64, B_);
  attn_kernel<<<attn_grid, 256>>>(out);
}

// round 2
// speedup vs baseline: 2.5542x; 2.5542x over previous
#include <cuda_runtime.h>

#define B_ 4
#define T_ 4096
#define C_ 512
#define H_ 64

// Projected k,q,v scratch [B,T,H] fp32
__device__ float g_k[B_ * T_ * H_];
__device__ float g_q[B_ * T_ * H_];
__device__ float g_v[B_ * T_ * H_];

// ---------------------------------------------------------------------------
// Helpers
// ---------------------------------------------------------------------------
__device__ __forceinline__ float to_tf32(float x) {
  unsigned u;
  asm("cvt.rna.tf32.f32 %0, %1;" : "=r"(u) : "f"(x));
  return __uint_as_float(u);
}

__device__ __forceinline__ void mma_tf32(float d[4], unsigned a0, unsigned a1,
                                         unsigned a2, unsigned a3, unsigned b0,
                                         unsigned b1) {
  asm volatile(
      "mma.sync.aligned.m16n8k8.row.col.f32.tf32.tf32.f32 "
      "{%0,%1,%2,%3}, {%4,%5,%6,%7}, {%8,%9}, {%0,%1,%2,%3};"
      : "+f"(d[0]), "+f"(d[1]), "+f"(d[2]), "+f"(d[3])
      : "r"(a0), "r"(a1), "r"(a2), "r"(a3), "r"(b0), "r"(b1));
}

__device__ __forceinline__ unsigned ldu(const float* p) {
  return __float_as_uint(*p);
}

// ---------------------------------------------------------------------------
// Kernel 1: QKV projection via tf32 mma. M=16384 N=64 K=512.
// BM=128, BK=32. 8 warps, warp w owns 16-row stripe. blockIdx.y picks k/q/v.
// ---------------------------------------------------------------------------
#define AS_STRIDE 36
#define WS_STRIDE 72

__global__ __launch_bounds__(256) void qkv_mma_kernel(
    const float* __restrict__ x,
    const float* __restrict__ Wk, const float* __restrict__ bk,
    const float* __restrict__ Wq, const float* __restrict__ bq,
    const float* __restrict__ Wv, const float* __restrict__ bv) {
  __shared__ float As[128 * AS_STRIDE];
  __shared__ float Ws[32 * WS_STRIDE];

  const float* W;
  const float* bias;
  float* out;
  if (blockIdx.y == 0)      { W = Wk; bias = bk; out = g_k; }
  else if (blockIdx.y == 1) { W = Wq; bias = bq; out = g_q; }
  else                      { W = Wv; bias = bv; out = g_v; }

  const int row0 = blockIdx.x * 128;
  const int tid = threadIdx.x;
  const int w = tid >> 5;
  const int lane = tid & 31;
  const int g = lane >> 2;   // groupID
  const int t = lane & 3;    // threadID in group

  float acc[8][4] = {};

  for (int kc = 0; kc < C_; kc += 32) {
    #pragma unroll
    for (int i = tid; i < 128 * 32; i += 256) {
      int r = i >> 5, c = i & 31;
      As[r * AS_STRIDE + c] = to_tf32(x[(size_t)(row0 + r) * C_ + kc + c]);
    }
    #pragma unroll
    for (int i = tid; i < 32 * 64; i += 256) {
      int r = i >> 6, c = i & 63;
      Ws[r * WS_STRIDE + c] = to_tf32(W[(kc + r) * H_ + c]);
    }
    __syncthreads();

    const float* arow = As + (16 * w) * AS_STRIDE;
    #pragma unroll
    for (int kk = 0; kk < 4; kk++) {
      unsigned a0 = ldu(arow + g * AS_STRIDE + 8 * kk + t);
      unsigned a1 = ldu(arow + (g + 8) * AS_STRIDE + 8 * kk + t);
      unsigned a2 = ldu(arow + g * AS_STRIDE + 8 * kk + t + 4);
      unsigned a3 = ldu(arow + (g + 8) * AS_STRIDE + 8 * kk + t + 4);
      #pragma unroll
      for (int nt = 0; nt < 8; nt++) {
        unsigned b0 = ldu(Ws + (8 * kk + t) * WS_STRIDE + 8 * nt + g);
        unsigned b1 = ldu(Ws + (8 * kk + t + 4) * WS_STRIDE + 8 * nt + g);
        mma_tf32(acc[nt], a0, a1, a2, a3, b0, b1);
      }
    }
    __syncthreads();
  }

  #pragma unroll
  for (int nt = 0; nt < 8; nt++) {
    int c0 = 8 * nt + 2 * t;
    float bc0 = bias[c0], bc1 = bias[c0 + 1];
    size_t r0 = (size_t)(row0 + 16 * w + g) * H_;
    size_t r1 = (size_t)(row0 + 16 * w + g + 8) * H_;
    out[r0 + c0]     = acc[nt][0] + bc0;
    out[r0 + c0 + 1] = acc[nt][1] + bc1;
    out[r1 + c0]     = acc[nt][2] + bc0;
    out[r1 + c0 + 1] = acc[nt][3] + bc1;
  }
}

// ---------------------------------------------------------------------------
// Kernel 2: flash attention, tf32 mma for both S = K·Qᵀ and O += P·V.
// BR=128 k-rows per block (8 warps × 16-row stripes), q-tiles of BC=64, H=64.
// ---------------------------------------------------------------------------
#define KS_STRIDE 68
#define QS_STRIDE 68
#define VS_STRIDE 72
#define PS_STRIDE 68
#define ATTN_SMEM_FLOATS (128 * KS_STRIDE + 64 * QS_STRIDE + 64 * VS_STRIDE + 128 * PS_STRIDE)
#define ATTN_SMEM_BYTES (ATTN_SMEM_FLOATS * 4)

__global__ __launch_bounds__(256) void attn_mma_kernel(float* __restrict__ out) {
  extern __shared__ float smem[];
  float* ks = smem;                        // [128][68]
  float* qs = ks + 128 * KS_STRIDE;        // [64][68]
  float* vs = qs + 64 * QS_STRIDE;         // [64][72]
  float* Ps = vs + 64 * VS_STRIDE;         // [128][68]

  const int b = blockIdx.y;
  const int row0 = blockIdx.x * 128;
  const int tid = threadIdx.x;
  const int w = tid >> 5;
  const int lane = tid & 31;
  const int g = lane >> 2;
  const int t = lane & 3;
  const float scale = 0.04419417382415922f;  // 512^-0.5

  const float* kg = g_k + (size_t)b * T_ * H_;
  const float* qg = g_q + (size_t)b * T_ * H_;
  const float* vg = g_v + (size_t)b * T_ * H_;

  // K tile loaded once, scale folded, tf32-rounded
  for (int i = tid; i < 128 * 64; i += 256) {
    int r = i >> 6, h = i & 63;
    ks[r * KS_STRIDE + h] = to_tf32(kg[(size_t)(row0 + r) * H_ + h] * scale);
  }

  float m0 = -1e30f, m1 = -1e30f, l0 = 0.0f, l1 = 0.0f;
  float oc[8][4] = {};

  const float* krow = ks + (16 * w) * KS_STRIDE;
  float* prow = Ps + (16 * w) * PS_STRIDE;

  for (int jt = 0; jt < T_; jt += 64) {
    __syncthreads();
    #pragma unroll
    for (int i = tid; i < 64 * 64; i += 256) {
      int j = i >> 6, h = i & 63;
      qs[j * QS_STRIDE + h] = to_tf32(qg[(size_t)(jt + j) * H_ + h]);
      vs[j * VS_STRIDE + h] = to_tf32(vg[(size_t)(jt + j) * H_ + h]);
    }
    __syncthreads();

    // ---- S = K · Qᵀ  (m=16 rows, n=64 q-cols, k=64 h) ----
    float sc[8][4] = {};
    #pragma unroll
    for (int kk = 0; kk < 8; kk++) {
      unsigned a0 = ldu(krow + g * KS_STRIDE + 8 * kk + t);
      unsigned a1 = ldu(krow + (g + 8) * KS_STRIDE + 8 * kk + t);
      unsigned a2 = ldu(krow + g * KS_STRIDE + 8 * kk + t + 4);
      unsigned a3 = ldu(krow + (g + 8) * KS_STRIDE + 8 * kk + t + 4);
      #pragma unroll
      for (int nt = 0; nt < 8; nt++) {
        unsigned b0 = ldu(qs + (8 * nt + g) * QS_STRIDE + 8 * kk + t);
        unsigned b1 = ldu(qs + (8 * nt + g) * QS_STRIDE + 8 * kk + t + 4);
        mma_tf32(sc[nt], a0, a1, a2, a3, b0, b1);
      }
    }

    // ---- online softmax over the 64 q-cols of this tile ----
    float mr0 = -1e30f, mr1 = -1e30f;
    #pragma unroll
    for (int nt = 0; nt < 8; nt++) {
      mr0 = fmaxf(mr0, fmaxf(sc[nt][0], sc[nt][1]));
      mr1 = fmaxf(mr1, fmaxf(sc[nt][2], sc[nt][3]));
    }
    mr0 = fmaxf(mr0, __shfl_xor_sync(0xffffffffu, mr0, 1));
    mr0 = fmaxf(mr0, __shfl_xor_sync(0xffffffffu, mr0, 2));
    mr1 = fmaxf(mr1, __shfl_xor_sync(0xffffffffu, mr1, 1));
    mr1 = fmaxf(mr1, __shfl_xor_sync(0xffffffffu, mr1, 2));

    float m0n = fmaxf(m0, mr0);
    float m1n = fmaxf(m1, mr1);
    float al0 = __expf(m0 - m0n);
    float al1 = __expf(m1 - m1n);

    float s0 = 0.0f, s1 = 0.0f;
    #pragma unroll
    for (int nt = 0; nt < 8; nt++) {
      float p0 = __expf(sc[nt][0] - m0n);
      float p1 = __expf(sc[nt][1] - m0n);
      float p2 = __expf(sc[nt][2] - m1n);
      float p3 = __expf(sc[nt][3] - m1n);
      s0 += p0 + p1;
      s1 += p2 + p3;
      int c0 = 8 * nt + 2 * t;
      prow[g * PS_STRIDE + c0]           = to_tf32(p0);
      prow[g * PS_STRIDE + c0 + 1]       = to_tf32(p1);
      prow[(g + 8) * PS_STRIDE + c0]     = to_tf32(p2);
      prow[(g + 8) * PS_STRIDE + c0 + 1] = to_tf32(p3);
    }
    s0 += __shfl_xor_sync(0xffffffffu, s0, 1);
    s0 += __shfl_xor_sync(0xffffffffu, s0, 2);
    s1 += __shfl_xor_sync(0xffffffffu, s1, 1);
    s1 += __shfl_xor_sync(0xffffffffu, s1, 2);

    l0 = l0 * al0 + s0;
    l1 = l1 * al1 + s1;
    m0 = m0n;
    m1 = m1n;
    #pragma unroll
    for (int nt = 0; nt < 8; nt++) {
      oc[nt][0] *= al0;
      oc[nt][1] *= al0;
      oc[nt][2] *= al1;
      oc[nt][3] *= al1;
    }
    __syncthreads();

    // ---- O += P · V  (m=16 rows, n=64 h, k=64 q) ----
    #pragma unroll
    for (int kk = 0; kk < 8; kk++) {
      unsigned a0 = ldu(prow + g * PS_STRIDE + 8 * kk + t);
      unsigned a1 = ldu(prow + (g + 8) * PS_STRIDE + 8 * kk + t);
      unsigned a2 = ldu(prow + g * PS_STRIDE + 8 * kk + t + 4);
      unsigned a3 = ldu(prow + (g + 8) * PS_STRIDE + 8 * kk + t + 4);
      #pragma unroll
      for (int nt = 0; nt < 8; nt++) {
        unsigned b0 = ldu(vs + (8 * kk + t) * VS_STRIDE + 8 * nt + g);
        unsigned b1 = ldu(vs + (8 * kk + t + 4) * VS_STRIDE + 8 * nt + g);
        mma_tf32(oc[nt], a0, a1, a2, a3, b0, b1);
      }
    }
  }

  // epilogue: normalize and store
  float inv0 = 1.0f / l0;
  float inv1 = 1.0f / l1;
  size_t r0 = ((size_t)b * T_ + row0 + 16 * w + g) * H_;
  size_t r1 = ((size_t)b * T_ + row0 + 16 * w + g + 8) * H_;
  #pragma unroll
  for (int nt = 0; nt < 8; nt++) {
    int c0 = 8 * nt + 2 * t;
    out[r0 + c0]     = oc[nt][0] * inv0;
    out[r0 + c0 + 1] = oc[nt][1] * inv0;
    out[r1 + c0]     = oc[nt][2] * inv1;
    out[r1 + c0 + 1] = oc[nt][3] * inv1;
  }
}

extern "C" void kernel_launch(void* const* d_in, const int* in_sizes, int n_in,
                              void* d_out, int out_size) {
  const float* x  = (const float*)d_in[0];
  const float* Wk = (const float*)d_in[1];
  const float* bk = (const float*)d_in[2];
  const float* Wq = (const float*)d_in[3];
  const float* bq = (const float*)d_in[4];
  const float* Wv = (const float*)d_in[5];
  const float* bv = (const float*)d_in[6];
  float* out = (float*)d_out;

  cudaFuncSetAttribute(attn_mma_kernel,
                       cudaFuncAttributeMaxDynamicSharedMemorySize,
                       ATTN_SMEM_BYTES);

  dim3 qkv_grid((B_ * T_) / 128, 3);
  qkv_mma_kernel<<<qkv_grid, 256>>>(x, Wk, bk, Wq, bq, Wv, bv);

  dim3 attn_grid(T_ / 128, B_);
  attn_mma_kernel<<<attn_grid, 256, ATTN_SMEM_BYTES>>>(out);
}

// round 3
// speedup vs baseline: 3.0751x; 1.2039x over previous
#include <cuda_runtime.h>

#define B_ 4
#define T_ 4096
#define C_ 512
#define H_ 64

// Projected tensors (written by qkv kernel, read by attn kernel):
//  g_k: scaled by C^-0.5, tf32-rounded, h-PERMUTED
//  g_q: tf32-rounded, h-PERMUTED
//  g_v: tf32-rounded, plain layout
__device__ float g_k[B_ * T_ * H_];
__device__ float g_q[B_ * T_ * H_];
__device__ float g_v[B_ * T_ * H_];

// ---------------------------------------------------------------------------
__device__ __forceinline__ float to_tf32(float x) {
  unsigned u;
  asm("cvt.rna.tf32.f32 %0, %1;" : "=r"(u) : "f"(x));
  return __uint_as_float(u);
}
__device__ __forceinline__ unsigned f2u(float x) { return __float_as_uint(x); }

__device__ __forceinline__ void mma_tf32(float d[4], unsigned a0, unsigned a1,
                                         unsigned a2, unsigned a3, unsigned b0,
                                         unsigned b1) {
  asm volatile(
      "mma.sync.aligned.m16n8k8.row.col.f32.tf32.tf32.f32 "
      "{%0,%1,%2,%3}, {%4,%5,%6,%7}, {%8,%9}, {%0,%1,%2,%3};"
      : "+f"(d[0]), "+f"(d[1]), "+f"(d[2]), "+f"(d[3])
      : "r"(a0), "r"(a1), "r"(a2), "r"(a3), "r"(b0), "r"(b1));
}

#define CP16(dst_u32, src_ptr) \
  asm volatile("cp.async.cg.shared.global [%0], [%1], 16;\n" ::"r"(dst_u32), "l"(src_ptr))
#define CPCOMMIT asm volatile("cp.async.commit_group;\n")
#define CPWAIT1 asm volatile("cp.async.wait_group 1;\n")
#define CPWAIT0 asm volatile("cp.async.wait_group 0;\n")

// h-permutation: within each 8-block, (t, t+4) pairs become adjacent (2t, 2t+1)
__device__ __forceinline__ int permh(int h) {
  return (h & ~7) | ((h & 3) << 1) | ((h >> 2) & 1);
}

// ---------------------------------------------------------------------------
// Fused QKV projection: M=16384, N=192 (k|q|v), K=512. One pass over x.
// 8 warps, warp owns 16-row stripe; BK=64.
// ---------------------------------------------------------------------------
#define QAS 68
#define QWS 200
#define QKV_SMEM_BYTES ((128 * QAS + 64 * QWS) * 4)

__global__ __launch_bounds__(256) void qkv_mma_kernel(
    const float* __restrict__ x,
    const float* __restrict__ Wk, const float* __restrict__ bk,
    const float* __restrict__ Wq, const float* __restrict__ bq,
    const float* __restrict__ Wv, const float* __restrict__ bv) {
  extern __shared__ float sm[];
  float* As = sm;                 // [128][QAS], x chunk, k-cols permuted
  float* Ws = sm + 128 * QAS;     // [64][QWS], W chunk, 192 cols

  const int row0 = blockIdx.x * 128;
  const int tid = threadIdx.x;
  const int w = tid >> 5;
  const int lane = tid & 31;
  const int g = lane >> 2;
  const int t = lane & 3;
  const float scale = 0.04419417382415922f;  // 512^-0.5

  float acc[24][4] = {};

  for (int kc = 0; kc < C_; kc += 64) {
    // x chunk [128][64], permuted k-cols
    #pragma unroll
    for (int i = tid; i < 128 * 16; i += 256) {
      int r = i >> 4, c4 = (i & 15) * 4;
      float4 xv = *(const float4*)&x[(size_t)(row0 + r) * C_ + kc + c4];
      As[r * QAS + permh(c4 + 0)] = to_tf32(xv.x);
      As[r * QAS + permh(c4 + 1)] = to_tf32(xv.y);
      As[r * QAS + permh(c4 + 2)] = to_tf32(xv.z);
      As[r * QAS + permh(c4 + 3)] = to_tf32(xv.w);
    }
    // W chunk [64][192] = [Wk*scale | Wq | Wv]
    #pragma unroll
    for (int i = tid; i < 64 * 48; i += 256) {
      int r = i / 48, cc = i % 48;
      int mat = cc >> 4, c4 = (cc & 15) * 4;
      const float* W = (mat == 0) ? Wk : ((mat == 1) ? Wq : Wv);
      float s = (mat == 0) ? scale : 1.0f;
      float4 wv = *(const float4*)&W[(size_t)(kc + r) * H_ + c4];
      float* dst = &Ws[r * QWS + mat * 64 + c4];
      dst[0] = to_tf32(wv.x * s);
      dst[1] = to_tf32(wv.y * s);
      dst[2] = to_tf32(wv.z * s);
      dst[3] = to_tf32(wv.w * s);
    }
    __syncthreads();

    const float* arow = As + (16 * w) * QAS;
    #pragma unroll
    for (int kk = 0; kk < 8; kk++) {
      float2 aA = *(const float2*)&arow[g * QAS + 8 * kk + 2 * t];
      float2 aB = *(const float2*)&arow[(g + 8) * QAS + 8 * kk + 2 * t];
      unsigned a0 = f2u(aA.x), a2 = f2u(aA.y);
      unsigned a1 = f2u(aB.x), a3 = f2u(aB.y);
      #pragma unroll
      for (int nt = 0; nt < 24; nt++) {
        unsigned b0 = f2u(Ws[(8 * kk + t) * QWS + 8 * nt + g]);
        unsigned b1 = f2u(Ws[(8 * kk + t + 4) * QWS + 8 * nt + g]);
        mma_tf32(acc[nt], a0, a1, a2, a3, b0, b1);
      }
    }
    __syncthreads();
  }

  // epilogue: bias add, tf32 round, permuted store for k/q, plain for v
  const int r0g = row0 + 16 * w + g;
  #pragma unroll
  for (int nt = 0; nt < 24; nt++) {
    int mat = nt >> 3;
    int c0 = (nt & 7) * 8 + 2 * t;  // col within matrix
    const float* bias = (mat == 0) ? bk : ((mat == 1) ? bq : bv);
    float s = (mat == 0) ? scale : 1.0f;
    float b0v = bias[c0] * s, b1v = bias[c0 + 1] * s;
    float* outm = (mat == 0) ? g_k : ((mat == 1) ? g_q : g_v);
    int cA, cB;
    if (mat < 2) { cA = permh(c0); cB = permh(c0 + 1); }
    else         { cA = c0;        cB = c0 + 1; }
    outm[(size_t)r0g * H_ + cA]       = to_tf32(acc[nt][0] + b0v);
    outm[(size_t)r0g * H_ + cB]       = to_tf32(acc[nt][1] + b1v);
    outm[(size_t)(r0g + 8) * H_ + cA] = to_tf32(acc[nt][2] + b0v);
    outm[(size_t)(r0g + 8) * H_ + cB] = to_tf32(acc[nt][3] + b1v);
  }
}

// ---------------------------------------------------------------------------
// Flash attention: BR=128 k-rows/block, 8 warps (16-row stripes), q-tiles of 64.
// S and PV on tf32 mma; PV A-fragments from S accumulators via shfl permute;
// q/v tiles double-buffered with cp.async.
// ---------------------------------------------------------------------------
#define KS_STRIDE 68
#define QS_STRIDE 68
#define VS_STRIDE 72
#define KS_FLOATS (128 * KS_STRIDE)
#define QS_FLOATS (64 * QS_STRIDE)
#define VS_FLOATS (64 * VS_STRIDE)
#define ATTN_SMEM_BYTES ((KS_FLOATS + 2 * QS_FLOATS + 2 * VS_FLOATS) * 4)

__device__ __forceinline__ void load_qv_tile(float* qbuf, float* vbuf,
                                             const float* qg, const float* vg,
                                             int jt, int tid) {
  const float* qsrc = qg + (size_t)jt * H_;
  const float* vsrc = vg + (size_t)jt * H_;
  #pragma unroll
  for (int i = tid; i < 2048; i += 256) {
    int j = (i & 1023) >> 4;
    int c = (i & 15) * 4;
    if (i < 1024) {
      unsigned d = (unsigned)__cvta_generic_to_shared(&qbuf[j * QS_STRIDE + c]);
      CP16(d, qsrc + (size_t)j * H_ + c);
    } else {
      unsigned d = (unsigned)__cvta_generic_to_shared(&vbuf[j * VS_STRIDE + c]);
      CP16(d, vsrc + (size_t)j * H_ + c);
    }
  }
}

__global__ __launch_bounds__(256) void attn_mma_kernel(float* __restrict__ out) {
  extern __shared__ float sm[];
  float* ks  = sm;                          // [128][68] permuted
  float* qs0 = ks + KS_FLOATS;              // [64][68] permuted, buf 0
  float* qs1 = qs0 + QS_FLOATS;             // buf 1
  float* vs0 = qs1 + QS_FLOATS;             // [64][72] plain, buf 0
  float* vs1 = vs0 + VS_FLOATS;             // buf 1

  const int b = blockIdx.y;
  const int row0 = blockIdx.x * 128;
  const int tid = threadIdx.x;
  const int w = tid >> 5;
  const int lane = tid & 31;
  const int g = lane >> 2;
  const int t = lane & 3;

  const float* kg = g_k + (size_t)b * T_ * H_;
  const float* qg = g_q + (size_t)b * T_ * H_;
  const float* vg = g_v + (size_t)b * T_ * H_;

  // preload tile 0
  load_qv_tile(qs0, vs0, qg, vg, 0, tid);
  CPCOMMIT;

  // K tile (pre-scaled, pre-permuted, tf32): plain float4 copy
  {
    const float4* kg4 = reinterpret_cast<const float4*>(kg + (size_t)row0 * H_);
    #pragma unroll
    for (int i = tid; i < 128 * 16; i += 256) {
      int r = i >> 4, c = i & 15;
      *(float4*)&ks[r * KS_STRIDE + 4 * c] = kg4[r * 16 + c];
    }
  }

  float m0 = -1e30f, m1 = -1e30f, l0 = 0.0f, l1 = 0.0f;
  float oc[8][4] = {};

  const float* krow = ks + (16 * w) * KS_STRIDE;
  const int NT = T_ / 64;

  for (int it = 0; it < NT; ++it) {
    __syncthreads();  // all threads done with tile it-1 (buffer being refilled)
    if (it + 1 < NT) {
      load_qv_tile(((it + 1) & 1) ? qs1 : qs0, ((it + 1) & 1) ? vs1 : vs0,
                   qg, vg, (it + 1) * 64, tid);
      CPCOMMIT;
      CPWAIT1;  // tile it arrived
    } else {
      CPWAIT0;
    }
    __syncthreads();

    const float* q = (it & 1) ? qs1 : qs0;
    const float* v = (it & 1) ? vs1 : vs0;

    // ---- S = K · Qᵀ ----
    float sc[8][4] = {};
    #pragma unroll
    for (int kk = 0; kk < 8; kk++) {
      float2 aA = *(const float2*)&krow[g * KS_STRIDE + 8 * kk + 2 * t];
      float2 aB = *(const float2*)&krow[(g + 8) * KS_STRIDE + 8 * kk + 2 * t];
      unsigned a0 = f2u(aA.x), a2 = f2u(aA.y);
      unsigned a1 = f2u(aB.x), a3 = f2u(aB.y);
      #pragma unroll
      for (int nt = 0; nt < 8; nt++) {
        float2 b01 = *(const float2*)&q[(8 * nt + g) * QS_STRIDE + 8 * kk + 2 * t];
        mma_tf32(sc[nt], a0, a1, a2, a3, f2u(b01.x), f2u(b01.y));
      }
    }

    // ---- online softmax (rows g / g+8 of warp stripe) ----
    float mr0 = -1e30f, mr1 = -1e30f;
    #pragma unroll
    for (int nt = 0; nt < 8; nt++) {
      mr0 = fmaxf(mr0, fmaxf(sc[nt][0], sc[nt][1]));
      mr1 = fmaxf(mr1, fmaxf(sc[nt][2], sc[nt][3]));
    }
    mr0 = fmaxf(mr0, __shfl_xor_sync(0xffffffffu, mr0, 1));
    mr0 = fmaxf(mr0, __shfl_xor_sync(0xffffffffu, mr0, 2));
    mr1 = fmaxf(mr1, __shfl_xor_sync(0xffffffffu, mr1, 1));
    mr1 = fmaxf(mr1, __shfl_xor_sync(0xffffffffu, mr1, 2));

    float m0n = fmaxf(m0, mr0);
    float m1n = fmaxf(m1, mr1);
    float al0 = __expf(m0 - m0n);
    float al1 = __expf(m1 - m1n);

    float s0 = 0.0f, s1 = 0.0f;
    #pragma unroll
    for (int nt = 0; nt < 8; nt++) {
      sc[nt][0] = __expf(sc[nt][0] - m0n);
      sc[nt][1] = __expf(sc[nt][1] - m0n);
      sc[nt][2] = __expf(sc[nt][2] - m1n);
      sc[nt][3] = __expf(sc[nt][3] - m1n);
      s0 += sc[nt][0] + sc[nt][1];
      s1 += sc[nt][2] + sc[nt][3];
    }
    s0 += __shfl_xor_sync(0xffffffffu, s0, 1);
    s0 += __shfl_xor_sync(0xffffffffu, s0, 2);
    s1 += __shfl_xor_sync(0xffffffffu, s1, 1);
    s1 += __shfl_xor_sync(0xffffffffu, s1, 2);

    l0 = l0 * al0 + s0;
    l1 = l1 * al1 + s1;
    m0 = m0n;
    m1 = m1n;
    #pragma unroll
    for (int nt = 0; nt < 8; nt++) {
      oc[nt][0] *= al0;
      oc[nt][1] *= al0;
      oc[nt][2] *= al1;
      oc[nt][3] *= al1;
    }

    // ---- O += P · V : A-fragments via shfl permute of S accumulators ----
    const int base = lane & ~3;
    const int sA = base + (t >> 1);
    const int sB = sA + 2;
    const bool odd = t & 1;
    #pragma unroll
    for (int kk = 0; kk < 8; kk++) {
      float c0 = sc[kk][0], c1 = sc[kk][1], c2 = sc[kk][2], c3 = sc[kk][3];
      float x0 = __shfl_sync(0xffffffffu, c0, sA);
      float x1 = __shfl_sync(0xffffffffu, c1, sA);
      float x2 = __shfl_sync(0xffffffffu, c2, sA);
      float x3 = __shfl_sync(0xffffffffu, c3, sA);
      float y0 = __shfl_sync(0xffffffffu, c0, sB);
      float y1 = __shfl_sync(0xffffffffu, c1, sB);
      float y2 = __shfl_sync(0xffffffffu, c2, sB);
      float y3 = __shfl_sync(0xffffffffu, c3, sB);
      unsigned a0 = f2u(to_tf32(odd ? x1 : x0));  // P[g][8kk+t]
      unsigned a1 = f2u(to_tf32(odd ? x3 : x2));  // P[g+8][8kk+t]
      unsigned a2 = f2u(to_tf32(odd ? y1 : y0));  // P[g][8kk+t+4]
      unsigned a3 = f2u(to_tf32(odd ? y3 : y2));  // P[g+8][8kk+t+4]
      #pragma unroll
      for (int nt = 0; nt < 8; nt++) {
        unsigned b0 = f2u(v[(8 * kk + t) * VS_STRIDE + 8 * nt + g]);
        unsigned b1 = f2u(v[(8 * kk + t + 4) * VS_STRIDE + 8 * nt + g]);
        mma_tf32(oc[nt], a0, a1, a2, a3, b0, b1);
      }
    }
  }

  // epilogue
  float inv0 = 1.0f / l0;
  float inv1 = 1.0f / l1;
  size_t r0 = ((size_t)b * T_ + row0 + 16 * w + g) * H_;
  size_t r1 = ((size_t)b * T_ + row0 + 16 * w + g + 8) * H_;
  #pragma unroll
  for (int nt = 0; nt < 8; nt++) {
    int c0 = 8 * nt + 2 * t;
    out[r0 + c0]     = oc[nt][0] * inv0;
    out[r0 + c0 + 1] = oc[nt][1] * inv0;
    out[r1 + c0]     = oc[nt][2] * inv1;
    out[r1 + c0 + 1] = oc[nt][3] * inv1;
  }
}

extern "C" void kernel_launch(void* const* d_in, const int* in_sizes, int n_in,
                              void* d_out, int out_size) {
  const float* x  = (const float*)d_in[0];
  const float* Wk = (const float*)d_in[1];
  const float* bk = (const float*)d_in[2];
  const float* Wq = (const float*)d_in[3];
  const float* bq = (const float*)d_in[4];
  const float* Wv = (const float*)d_in[5];
  const float* bv = (const float*)d_in[6];
  float* out = (float*)d_out;

  static bool attr_set = false;
  if (!attr_set) {
    cudaFuncSetAttribute(qkv_mma_kernel,
                         cudaFuncAttributeMaxDynamicSharedMemorySize,
                         QKV_SMEM_BYTES);
    cudaFuncSetAttribute(attn_mma_kernel,
                         cudaFuncAttributeMaxDynamicSharedMemorySize,
                         ATTN_SMEM_BYTES);
    attr_set = true;
  }

  qkv_mma_kernel<<<(B_ * T_) / 128, 256, QKV_SMEM_BYTES>>>(x, Wk, bk, Wq, bq,
                                                           Wv, bv);
  dim3 attn_grid(T_ / 128, B_);
  attn_mma_kernel<<<attn_grid, 256, ATTN_SMEM_BYTES>>>(out);
}